// round 6
// baseline (speedup 1.0000x reference)
#include <cuda_runtime.h>

// Problem shapes (fixed)
#define BB 32
#define NN 4096
#define DD 8
#define NEE 2048
#define DEE 4

// Device scratch (static globals; no allocation)
__device__ unsigned g_mask_int[NN];
__device__ unsigned g_mask_ext[NEE];
__device__ unsigned char g_del_int[NN];
__device__ unsigned char g_del_ext[NEE];
__device__ int g_list_int[BB][4352];
__device__ int g_list_ext[BB][2304];
__device__ int g_cnt_int[BB];
__device__ int g_cnt_ext[BB];

// ---------------------------------------------------------------------------
// Kernel 1: spike generation (thread per (b,n)) + delay decode + mask zero.
// ---------------------------------------------------------------------------
__global__ void k_spike(const float* __restrict__ V, const float* __restrict__ a,
                        const float* __restrict__ dmap_int,
                        const float* __restrict__ dmap_ext,
                        float* __restrict__ out) {
    int idx = blockIdx.x * blockDim.x + threadIdx.x;   // 0 .. B*N-1
    float v  = V[idx];
    float aa = a[idx];
    float th = __fadd_rn(1.0f, __fmul_rn(1.8f, aa));
    float x  = (__fadd_rn(v, -th) >= 0.0f) ? 1.0f : 0.0f;
    out[idx] = x;                                       // row 0: X
    out[2 * BB * NN + idx] = 0.98f * aa + x;            // row 2: a_new

    if (idx < NN) {
        int del = 0;
#pragma unroll
        for (int d = 0; d < DD; d++)
            if (dmap_int[d * NN + idx] > 0.5f) del = d;
        g_del_int[idx] = (unsigned char)del;
        g_mask_int[idx] = 0u;
    }
    if (idx < NEE) {
        int del = 0;
#pragma unroll
        for (int d = 0; d < DEE; d++)
            if (dmap_ext[d * NEE + idx] > 0.5f) del = d;
        g_del_ext[idx] = (unsigned char)del;
        g_mask_ext[idx] = 0u;
    }
}

// ---------------------------------------------------------------------------
// Kernel 2: mask build via predicated atomicOr (commutative -> deterministic).
// ---------------------------------------------------------------------------
__global__ void __launch_bounds__(256) k_mask2(
        const float* __restrict__ Xd, const float* __restrict__ Xext,
        const float* __restrict__ out /* row 0 = X */) {
    int i = blockIdx.x * blockDim.x + threadIdx.x;      // source 0..N-1
    int b = blockIdx.y;                                 // batch

    {
        int del = g_del_int[i];
        float xs = (del == 0) ? out[b * NN + i]
                              : Xd[(size_t)(del - 1) * BB * NN + b * NN + i];
        if (xs > 0.5f) atomicOr(&g_mask_int[i], 1u << b);
    }
    if (i < NEE) {
        int del = g_del_ext[i];
        float xs = Xext[(size_t)del * BB * NEE + b * NEE + i];
        if (xs > 0.5f) atomicOr(&g_mask_ext[i], 1u << b);
    }
}

// ---------------------------------------------------------------------------
// Kernel 3: parallel deterministic compaction. One block (8 warps) per batch.
// Lists padded to a multiple of 16 with -1 sentinels (window count even).
// ---------------------------------------------------------------------------
__global__ void __launch_bounds__(256) k_compact() {
    int b = blockIdx.x;            // 0..31
    int tid = threadIdx.x;
    int w = tid >> 5, lane = tid & 31;
    unsigned lt = (lane == 0) ? 0u : (0xffffffffu >> (32 - lane));

    __shared__ int wcnt[8], wbase[8], s_total;

    // ---- internal ----
    {
        int cnt = 0;
#pragma unroll
        for (int r = 0; r < 16; r++) {
            int i = (w * 16 + r) * 32 + lane;
            bool act = (g_mask_int[i] >> b) & 1u;
            cnt += __popc(__ballot_sync(0xffffffffu, act));
        }
        if (lane == 0) wcnt[w] = cnt;
        __syncthreads();
        if (tid == 0) {
            int s = 0;
#pragma unroll
            for (int j = 0; j < 8; j++) { wbase[j] = s; s += wcnt[j]; }
            s_total = s;
        }
        __syncthreads();
        int base = wbase[w];
#pragma unroll
        for (int r = 0; r < 16; r++) {
            int i = (w * 16 + r) * 32 + lane;
            bool act = (g_mask_int[i] >> b) & 1u;
            unsigned bal = __ballot_sync(0xffffffffu, act);
            if (act) g_list_int[b][base + __popc(bal & lt)] = i;
            base += __popc(bal);
        }
        int t = s_total;
        int padded = (t + 15) & ~15;
        if (t + tid < padded) g_list_int[b][t + tid] = -1;
        if (tid == 0) g_cnt_int[b] = padded;
        __syncthreads();
    }

    // ---- external ----
    {
        int cnt = 0;
#pragma unroll
        for (int r = 0; r < 8; r++) {
            int i = (w * 8 + r) * 32 + lane;
            bool act = (g_mask_ext[i] >> b) & 1u;
            cnt += __popc(__ballot_sync(0xffffffffu, act));
        }
        if (lane == 0) wcnt[w] = cnt;
        __syncthreads();
        if (tid == 0) {
            int s = 0;
#pragma unroll
            for (int j = 0; j < 8; j++) { wbase[j] = s; s += wcnt[j]; }
            s_total = s;
        }
        __syncthreads();
        int base = wbase[w];
#pragma unroll
        for (int r = 0; r < 8; r++) {
            int i = (w * 8 + r) * 32 + lane;
            bool act = (g_mask_ext[i] >> b) & 1u;
            unsigned bal = __ballot_sync(0xffffffffu, act);
            if (act) g_list_ext[b][base + __popc(bal & lt)] = i;
            base += __popc(bal);
        }
        int t = s_total;
        int padded = (t + 15) & ~15;
        if (t + tid < padded) g_list_ext[b][t + tid] = -1;
        if (tid == 0) g_cnt_ext[b] = padded;
    }
}

// ---------------------------------------------------------------------------
// Kernel 4: software-pipelined sparse row-gather + membrane update.
// Ping-pong 8-wide load windows: next window's indices are fetched (LDS.128)
// and its LDGs ISSUED before the current window's values are consumed, so
// 8-16 loads stay continuously in flight per thread.
// ---------------------------------------------------------------------------
__device__ __forceinline__ void prefetch8(const int* __restrict__ sl, int k,
                                          const float* __restrict__ Wn,
                                          int* __restrict__ e,
                                          float* __restrict__ w) {
    int4 p0 = *reinterpret_cast<const int4*>(sl + k);
    int4 p1 = *reinterpret_cast<const int4*>(sl + k + 4);
    e[0] = p0.x; e[1] = p0.y; e[2] = p0.z; e[3] = p0.w;
    e[4] = p1.x; e[5] = p1.y; e[6] = p1.z; e[7] = p1.w;
#pragma unroll
    for (int u = 0; u < 8; u++)
        w[u] = (e[u] >= 0) ? __ldg(Wn + (size_t)e[u] * NN) : 0.0f;
}

__global__ void __launch_bounds__(128, 4) k_gather(
        const float* __restrict__ V,
        const float* __restrict__ W_int,
        const float* __restrict__ W_ext,
        float* __restrict__ out) {
    __shared__ alignas(16) int s_int[4352];
    __shared__ alignas(16) int s_ext[2304];

    int b = blockIdx.y;
    const int cnt_i = g_cnt_int[b];
    const int cnt_e = g_cnt_ext[b];
    for (int k = threadIdx.x; k < cnt_i; k += 128) s_int[k] = g_list_int[b][k];
    for (int k = threadIdx.x; k < cnt_e; k += 128) s_ext[k] = g_list_ext[b][k];
    __syncthreads();

    int n = blockIdx.x * 128 + threadIdx.x;   // column
    int idx = b * NN + n;

    float x = out[idx];                       // X (row 0)
    float acc0 = 0.95f * V[idx] * (1.0f - x);
    float acc1 = 0.0f, acc2 = 0.0f, acc3 = 0.0f;

    // ---- internal (cnt_i multiple of 16 => even number of 8-windows) ----
    if (cnt_i > 0) {
        const float* Wn = W_int + n;
        int eA[8], eB[8];
        float wA[8], wB[8];
        prefetch8(s_int, 0, Wn, eA, wA);
        for (int k = 8; k < cnt_i; k += 16) {
            prefetch8(s_int, k, Wn, eB, wB);
            acc0 += wA[0]; acc1 += wA[1]; acc2 += wA[2]; acc3 += wA[3];
            acc0 += wA[4]; acc1 += wA[5]; acc2 += wA[6]; acc3 += wA[7];
            if (k + 8 < cnt_i) prefetch8(s_int, k + 8, Wn, eA, wA);
            acc0 += wB[0]; acc1 += wB[1]; acc2 += wB[2]; acc3 += wB[3];
            acc0 += wB[4]; acc1 += wB[5]; acc2 += wB[6]; acc3 += wB[7];
        }
    }

    // ---- external ----
    if (cnt_e > 0) {
        const float* Wn = W_ext + n;
        int eA[8], eB[8];
        float wA[8], wB[8];
        prefetch8(s_ext, 0, Wn, eA, wA);
        for (int k = 8; k < cnt_e; k += 16) {
            prefetch8(s_ext, k, Wn, eB, wB);
            acc0 += wA[0]; acc1 += wA[1]; acc2 += wA[2]; acc3 += wA[3];
            acc0 += wA[4]; acc1 += wA[5]; acc2 += wA[6]; acc3 += wA[7];
            if (k + 8 < cnt_e) prefetch8(s_ext, k + 8, Wn, eA, wA);
            acc0 += wB[0]; acc1 += wB[1]; acc2 += wB[2]; acc3 += wB[3];
            acc0 += wB[4]; acc1 += wB[5]; acc2 += wB[6]; acc3 += wB[7];
        }
    }

    out[BB * NN + idx] = (acc0 + acc1) + (acc2 + acc3);   // row 1: V_new
}

// ---------------------------------------------------------------------------
extern "C" void kernel_launch(void* const* d_in, const int* in_sizes, int n_in,
                              void* d_out, int out_size) {
    const float* V        = (const float*)d_in[0];   // [B,N]
    const float* a        = (const float*)d_in[1];   // [B,N]
    const float* Xd       = (const float*)d_in[2];   // [D,B,N]
    const float* Xext     = (const float*)d_in[3];   // [DE,B,NE]
    const float* W_int    = (const float*)d_in[4];   // [N,N]
    const float* W_ext    = (const float*)d_in[5];   // [NE,N]
    const float* dmap_int = (const float*)d_in[6];   // [D,N]
    const float* dmap_ext = (const float*)d_in[7];   // [DE,NE]
    float* out = (float*)d_out;                      // [3,B,N]

    k_spike<<<(BB * NN) / 256, 256>>>(V, a, dmap_int, dmap_ext, out);
    dim3 mgrid(NN / 256, BB);
    k_mask2<<<mgrid, 256>>>(Xd, Xext, out);
    k_compact<<<BB, 256>>>();
    dim3 grid(NN / 128, BB);
    k_gather<<<grid, 128>>>(V, W_int, W_ext, out);
}